// round 5
// baseline (speedup 1.0000x reference)
#include <cuda_runtime.h>
#include <cuda_bf16.h>
#include <math.h>

// Problem dims
#define NT_ 730
#define NS_ 2000
#define NH_ 16
#define NG_ 32
#define NR_ 15

// ---------------- scratch (device globals; no allocations allowed) ----------------
__device__ float g_hfc [NS_ * 256];          // tanh hidden of fc
__device__ float g_hR  [NS_ * 256];          // tanh hidden of fcR
__device__ float g_base1[NS_ * 256];         // fcT1 layer1 basin-constant preact (incl bias)
__device__ float g_base2[NS_ * 256];         // fcT2 layer1 basin-constant preact (incl bias)
__device__ float g_params[8][NS_ * NH_];     // k1,k2,k23,k3,gl,qb,ge1,ge2  [p][s*16+h]
__device__ float g_rr  [NS_ * NH_ * 16];     // ga*relu(wR) taps, lag-indexed, padded to 16
__device__ float g_vi  [NT_ * NS_ * NH_];    // 93.4 MB
__device__ float g_vk  [NT_ * NS_ * NH_];
__device__ float g_vm  [NT_ * NS_ * NH_];

// ---------------- helpers ----------------
__device__ __forceinline__ float tanh_fast(float x) {
    // (e^{2x}-1)/(e^{2x}+1), clamped; rel err ~1e-6
    x = fminf(fmaxf(x, -10.f), 10.f);
    float e = __expf(x + x);
    return __fdividef(e - 1.f, e + 1.f);
}

__device__ __forceinline__ unsigned long long pack2(float a, float b) {
    unsigned long long r;
    asm("mov.b64 %0, {%1, %2};" : "=l"(r) : "r"(__float_as_uint(a)), "r"(__float_as_uint(b)));
    return r;
}
__device__ __forceinline__ void unpack2(unsigned long long v, float& a, float& b) {
    unsigned int lo, hi;
    asm("mov.b64 {%0, %1}, %2;" : "=r"(lo), "=r"(hi) : "l"(v));
    a = __uint_as_float(lo);
    b = __uint_as_float(hi);
}
__device__ __forceinline__ void fma2(unsigned long long& d, unsigned long long a, unsigned long long b) {
    asm("fma.rn.f32x2 %0, %1, %2, %0;" : "+l"(d) : "l"(a), "l"(b));
}

// ============================================================================
// Kernel 1a: per-basin hidden activations + time-invariant layer-1 bases
// 8 basins per block, 256 threads (thread = hidden unit j)
// ============================================================================
__global__ void __launch_bounds__(256) k_hidden(
    const float* __restrict__ xc,
    const float* __restrict__ fc_W1,  const float* __restrict__ fc_b1,
    const float* __restrict__ fcR_W1, const float* __restrict__ fcR_b1,
    const float* __restrict__ fcT1_W1, const float* __restrict__ fcT1_b1,
    const float* __restrict__ fcT2_W1, const float* __restrict__ fcT2_b1)
{
    __shared__ float xcs[8][NG_];
    const int tid = threadIdx.x;
    const int s0  = blockIdx.x * 8;
    xcs[tid >> 5][tid & 31] = xc[s0 * NG_ + tid];
    __syncthreads();

    const int j = tid;
    float acc[8];

    // fc hidden
    {
        float b = fc_b1[j];
#pragma unroll
        for (int i = 0; i < 8; i++) acc[i] = b;
        const float4* row = (const float4*)(fc_W1 + j * NG_);
#pragma unroll
        for (int q = 0; q < 8; q++) {
            float4 w = row[q];
#pragma unroll
            for (int i = 0; i < 8; i++) {
                acc[i] = fmaf(w.x, xcs[i][4*q+0], acc[i]);
                acc[i] = fmaf(w.y, xcs[i][4*q+1], acc[i]);
                acc[i] = fmaf(w.z, xcs[i][4*q+2], acc[i]);
                acc[i] = fmaf(w.w, xcs[i][4*q+3], acc[i]);
            }
        }
#pragma unroll
        for (int i = 0; i < 8; i++) g_hfc[(s0 + i) * 256 + j] = tanhf(acc[i]);
    }
    // fcR hidden
    {
        float b = fcR_b1[j];
#pragma unroll
        for (int i = 0; i < 8; i++) acc[i] = b;
        const float4* row = (const float4*)(fcR_W1 + j * NG_);
#pragma unroll
        for (int q = 0; q < 8; q++) {
            float4 w = row[q];
#pragma unroll
            for (int i = 0; i < 8; i++) {
                acc[i] = fmaf(w.x, xcs[i][4*q+0], acc[i]);
                acc[i] = fmaf(w.y, xcs[i][4*q+1], acc[i]);
                acc[i] = fmaf(w.z, xcs[i][4*q+2], acc[i]);
                acc[i] = fmaf(w.w, xcs[i][4*q+3], acc[i]);
            }
        }
#pragma unroll
        for (int i = 0; i < 8; i++) g_hR[(s0 + i) * 256 + j] = tanhf(acc[i]);
    }
    // fcT1 base (cols 1..32, + bias)
    {
        float b = fcT1_b1[j];
#pragma unroll
        for (int i = 0; i < 8; i++) acc[i] = b;
        const float* row = fcT1_W1 + j * 33 + 1;
#pragma unroll
        for (int g = 0; g < NG_; g++) {
            float w = row[g];
#pragma unroll
            for (int i = 0; i < 8; i++) acc[i] = fmaf(w, xcs[i][g], acc[i]);
        }
#pragma unroll
        for (int i = 0; i < 8; i++) g_base1[(s0 + i) * 256 + j] = acc[i];
    }
    // fcT2 base (cols 3..34, + bias)
    {
        float b = fcT2_b1[j];
#pragma unroll
        for (int i = 0; i < 8; i++) acc[i] = b;
        const float* row = fcT2_W1 + j * 35 + 3;
#pragma unroll
        for (int g = 0; g < NG_; g++) {
            float w = row[g];
#pragma unroll
            for (int i = 0; i < 8; i++) acc[i] = fmaf(w, xcs[i][g], acc[i]);
        }
#pragma unroll
        for (int i = 0; i < 8; i++) g_base2[(s0 + i) * 256 + j] = acc[i];
    }
}

// ============================================================================
// Kernel 1b: per-basin output layers -> scan params + routing taps
// 8 basins per block, 256 threads
// ============================================================================
__global__ void __launch_bounds__(256) k_outputs(
    const float* __restrict__ fc_W2,  const float* __restrict__ fc_b2,
    const float* __restrict__ fcR_W2, const float* __restrict__ fcR_b2)
{
    __shared__ float hf[8][256];
    __shared__ float hr[8][256];
    __shared__ float w8[8][160];
    __shared__ float r8[8][240];
    __shared__ float ga8[8][NH_];

    const int tid = threadIdx.x;
    const int s0  = blockIdx.x * 8;

    for (int idx = tid; idx < 2048; idx += 256) {
        int b = idx >> 8, j = idx & 255;
        hf[b][j] = g_hfc[(s0 + b) * 256 + j];
        hr[b][j] = g_hR [(s0 + b) * 256 + j];
    }
    __syncthreads();

    if (tid < 160) {
        const int o = tid;
        float acc[8];
        float bb = fc_b2[o];
#pragma unroll
        for (int i = 0; i < 8; i++) acc[i] = bb;
        const float4* row = (const float4*)(fc_W2 + o * 256);
        for (int q = 0; q < 64; q++) {
            float4 w = row[q];
#pragma unroll
            for (int i = 0; i < 8; i++) {
                acc[i] = fmaf(w.x, hf[i][4*q+0], acc[i]);
                acc[i] = fmaf(w.y, hf[i][4*q+1], acc[i]);
                acc[i] = fmaf(w.z, hf[i][4*q+2], acc[i]);
                acc[i] = fmaf(w.w, hf[i][4*q+3], acc[i]);
            }
        }
#pragma unroll
        for (int i = 0; i < 8; i++) w8[i][o] = acc[i];
    }
    if (tid < 240) {
        const int o = tid;
        float acc[8];
        float bb = fcR_b2[o];
#pragma unroll
        for (int i = 0; i < 8; i++) acc[i] = bb;
        const float4* row = (const float4*)(fcR_W2 + o * 256);
        for (int q = 0; q < 64; q++) {
            float4 w = row[q];
#pragma unroll
            for (int i = 0; i < 8; i++) {
                acc[i] = fmaf(w.x, hr[i][4*q+0], acc[i]);
                acc[i] = fmaf(w.y, hr[i][4*q+1], acc[i]);
                acc[i] = fmaf(w.z, hr[i][4*q+2], acc[i]);
                acc[i] = fmaf(w.w, hr[i][4*q+3], acc[i]);
            }
        }
#pragma unroll
        for (int i = 0; i < 8; i++) r8[i][o] = fmaxf(acc[i], 0.f);
    }
    __syncthreads();

    if (tid < 128) {
        const int b = tid >> 4, h = tid & 15;
        const float* wb = w8[b];
        float k1  = 1.f / (1.f + expf(-wb[16  + h]));
        float k2  = 1.f / (1.f + expf(-wb[32  + h]));
        float k23 = 1.f / (1.f + expf(-wb[48  + h]));
        float k3  = (1.f / (1.f + expf(-wb[64 + h]))) * 0.1f;
        float gl  = expf(wb[80 + h]) * 2.f;
        float qb  = fmaxf(wb[112 + h], 0.f);
        float ge1 = fmaxf(wb[128 + h], 0.f);
        float ge2 = fmaxf(wb[144 + h], 0.f);
        // softmax over the 16 ga logits
        float m = wb[96];
        for (int i = 1; i < 16; i++) m = fmaxf(m, wb[96 + i]);
        float sum = 0.f;
        for (int i = 0; i < 16; i++) sum += expf(wb[96 + i] - m);
        float ga = expf(wb[96 + h] - m) / sum;
        ga8[b][h] = ga;

        const int lane = (s0 + b) * NH_ + h;
        g_params[0][lane] = k1;
        g_params[1][lane] = k2;
        g_params[2][lane] = k23;
        g_params[3][lane] = k3;
        g_params[4][lane] = gl;
        g_params[5][lane] = qb;
        g_params[6][lane] = ge1;
        g_params[7][lane] = ge2;
        g_rr[lane * 16 + 15] = 0.f;
    }
    __syncthreads();

    // rr[lag d] = ga * r[h*15 + (14-d)]   (XLA conv is cross-correlation, left pad nr-1)
    for (int idx = tid; idx < 8 * 240; idx += 256) {
        int b = idx / 240, o = idx % 240;
        int h = o / NR_, jj = o % NR_;
        int lane = (s0 + b) * NH_ + h;
        g_rr[lane * 16 + (14 - jj)] = ga8[b][h] * r8[b][o];
    }
}

// ============================================================================
// Kernel 2: per-(t,s) MLPs -> vi, vk, vm   (the dominant GEMM-like kernel)
// block = (basin s, 256 timesteps); FFMA2-packed layer-2
// ============================================================================
#define K2_SMEM_BYTES ((256 * 48 + 256 * 8 + 48) * 4)

__global__ void __launch_bounds__(256) k_mlp(
    const float* __restrict__ x,
    const float* __restrict__ fcT1_W1, const float* __restrict__ fcT1_W2,
    const float* __restrict__ fcT1_b2,
    const float* __restrict__ fcT2_W1, const float* __restrict__ fcT2_W2,
    const float* __restrict__ fcT2_b2)
{
    extern __shared__ float sm[];
    float* W_sm  = sm;                 // [256][48]  (32 h1-weights | 16 h2-weights) per j
    float* coef  = sm + 256 * 48;      // [256][8]   {base1, c1, base2, d0, d1, d2, 0, 0}
    float* biasS = coef + 256 * 8;     // [48]

    const int tid = threadIdx.x;
    const int s   = blockIdx.x;
    const int t0  = blockIdx.y << 8;

    for (int idx = tid; idx < 32 * 256; idx += 256) {
        int k = idx >> 8, j = idx & 255;
        W_sm[j * 48 + k] = fcT1_W2[idx];           // fcT1_W2[k][j]
    }
    for (int idx = tid; idx < 16 * 256; idx += 256) {
        int k = idx >> 8, j = idx & 255;
        W_sm[j * 48 + 32 + k] = fcT2_W2[idx];      // fcT2_W2[k][j], k<16 (17th unused)
    }
    {
        int j = tid;
        float* c = coef + j * 8;
        c[0] = g_base1[s * 256 + j];
        c[1] = fcT1_W1[j * 33];        // LAI coefficient
        c[2] = g_base2[s * 256 + j];
        c[3] = fcT2_W1[j * 35 + 0];    // R
        c[4] = fcT2_W1[j * 35 + 1];    // T1
        c[5] = fcT2_W1[j * 35 + 2];    // T2
        c[6] = 0.f; c[7] = 0.f;
    }
    if (tid < 32) biasS[tid]      = fcT1_b2[tid];
    if (tid < 16) biasS[32 + tid] = fcT2_b2[tid];
    __syncthreads();

    const int t = t0 + tid;
    const bool act = (t < NT_);
    float LAI = 0.f, Rv = 0.f, Ta = 0.f, Tb = 0.f;
    if (act) {
        int bi = (t * NS_ + s) * 6;
        Ta  = x[bi + 2];
        Tb  = x[bi + 3];
        Rv  = x[bi + 4];
        LAI = x[bi + 5];
    }

    unsigned long long acc[24];
#pragma unroll
    for (int i = 0; i < 24; i++) acc[i] = 0ULL;

#pragma unroll 2
    for (int j = 0; j < 256; j++) {
        const float4* c4 = (const float4*)(coef + j * 8);
        float4 cA = c4[0];
        float4 cB = c4[1];
        float h1 = tanh_fast(fmaf(LAI, cA.y, cA.x));
        float p2 = fmaf(Rv, cA.w, cA.z);
        p2 = fmaf(Ta, cB.x, p2);
        p2 = fmaf(Tb, cB.y, p2);
        float h2 = tanh_fast(p2);
        unsigned long long hh1 = pack2(h1, h1);
        unsigned long long hh2 = pack2(h2, h2);
        const ulonglong2* wrow = (const ulonglong2*)(W_sm + j * 48);
#pragma unroll
        for (int q = 0; q < 8; q++) {
            ulonglong2 wv = wrow[q];
            fma2(acc[2*q + 0], wv.x, hh1);
            fma2(acc[2*q + 1], wv.y, hh1);
        }
#pragma unroll
        for (int q = 8; q < 12; q++) {
            ulonglong2 wv = wrow[q];
            fma2(acc[2*q + 0], wv.x, hh2);
            fma2(acc[2*q + 1], wv.y, hh2);
        }
    }

    if (act) {
        float o[48];
#pragma unroll
        for (int p = 0; p < 24; p++) unpack2(acc[p], o[2*p], o[2*p + 1]);

        const int base = (t * NS_ + s) * NH_;
        const float inv6 = 1.f / 6.f;
#pragma unroll
        for (int kk = 0; kk < 16; kk += 4) {
            float4 v;
            v.x = __saturatef(fmaf(o[kk+0] + biasS[kk+0], inv6, 0.5f));
            v.y = __saturatef(fmaf(o[kk+1] + biasS[kk+1], inv6, 0.5f));
            v.z = __saturatef(fmaf(o[kk+2] + biasS[kk+2], inv6, 0.5f));
            v.w = __saturatef(fmaf(o[kk+3] + biasS[kk+3], inv6, 0.5f));
            *(float4*)(g_vi + base + kk) = v;
        }
#pragma unroll
        for (int kk = 0; kk < 16; kk += 4) {
            float4 v;
            v.x = __saturatef(fmaf(o[16+kk+0] + biasS[16+kk+0], inv6, 0.5f));
            v.y = __saturatef(fmaf(o[16+kk+1] + biasS[16+kk+1], inv6, 0.5f));
            v.z = __saturatef(fmaf(o[16+kk+2] + biasS[16+kk+2], inv6, 0.5f));
            v.w = __saturatef(fmaf(o[16+kk+3] + biasS[16+kk+3], inv6, 0.5f));
            *(float4*)(g_vk + base + kk) = v;
        }
#pragma unroll
        for (int kk = 0; kk < 16; kk += 4) {
            float4 v;
            v.x = __expf(2.f * (o[32+kk+0] + biasS[32+kk+0]));
            v.y = __expf(2.f * (o[32+kk+1] + biasS[32+kk+1]));
            v.z = __expf(2.f * (o[32+kk+2] + biasS[32+kk+2]));
            v.w = __expf(2.f * (o[32+kk+3] + biasS[32+kk+3]));
            *(float4*)(g_vm + base + kk) = v;
        }
    }
}

// ============================================================================
// Kernel 3: sequential scan over t, fused causal routing conv + ga-weighted
// reduction over h. One thread per (s,h) lane; 16-lane shuffle reduce.
// ============================================================================
__global__ void __launch_bounds__(256) k_scan(
    const float* __restrict__ x, float* __restrict__ out)
{
    const int lane = blockIdx.x * 256 + threadIdx.x;   // 0..31999
    const int s = lane >> 4;
    const int h = lane & 15;

    const float k1  = g_params[0][lane];
    const float k2  = g_params[1][lane];
    const float k23 = g_params[2][lane];
    const float k3  = g_params[3][lane];
    const float gl  = g_params[4][lane];
    const float qb  = g_params[5][lane];
    const float ge1 = g_params[6][lane];
    const float ge2 = g_params[7][lane];

    float rr[15];
#pragma unroll
    for (int d = 0; d < 15; d++) rr[d] = g_rr[lane * 16 + d];

    float S0 = 0.f, Sv = 0.f, S2 = 0.f, S3 = 0.f;
    float ring[14];
#pragma unroll
    for (int d = 0; d < 14; d++) ring[d] = 0.f;

    const float inv_pi = 1.f / 3.1415f;

    for (int t = 0; t < NT_; t++) {
        const int idx = t * NS_ + s;
        const int xb  = idx * 6;
        const float P  = __ldg(x + xb + 0);
        const float E  = __ldg(x + xb + 1);
        const float Ta = __ldg(x + xb + 2);
        const float Tb = __ldg(x + xb + 3);
        const int vb = idx * NH_ + h;
        const float vi = g_vi[vb];
        const float vk = g_vk[vb];
        const float vm = g_vm[vb];

        // snow/rain partition vp
        float den = Tb - Ta;
        float ra  = (Ta + Tb) / (den == 0.f ? 1.f : den);
        ra = fminf(fmaxf(ra, -1.f), 1.f);
        if (Ta >= 0.f || Tb <= 0.f) ra = 0.f;
        float vp = 1.f - acosf(ra) * inv_pi;
        if (Ta >= 0.f) vp = 1.f;
        if (Tb <= 0.f) vp = 0.f;

        float Ps  = P * (1.f - vp);
        float Pl  = P * vp;
        float Pl1 = Pl * (1.f - vi);
        float Pl2 = Pl * vi;
        float Ev1 = E * ge1;
        float Ev2 = E * ge2;

        float H0  = S0 + Ps;
        float qSm = fminf(H0, vm);
        float Hv  = fmaxf(Sv + Pl1 - Ev1, 0.f);
        float qv  = Sv * vk;
        float H2  = fmaxf(S2 + qSm + qv - Ev2 + Pl2, 0.f);
        float x1  = H2 - gl;
        float Q1  = (x1 > 0.f) ? __powf(x1, k1) : 0.f;
        float q2  = fminf(H2, gl) * k2;
        float Q2  = q2 * (1.f - k23);
        float H3  = S3 + q2 * k23;
        float Q3  = fmaf(H3, k3, qb);

        S0 = H0 - qSm;
        Sv = Hv - qv;
        S2 = H2 - Q1 - q2;
        S3 = H3 - Q3;

        float Qs = Q1 + Q2 + Q3;

        // causal conv against rr (lag 0..14) + shift ring
        float p = rr[0] * Qs;
#pragma unroll
        for (int d = 1; d < 15; d++) p = fmaf(rr[d], ring[d - 1], p);
#pragma unroll
        for (int d = 13; d > 0; d--) ring[d] = ring[d - 1];
        ring[0] = Qs;

        // reduce over the 16 bucket lanes of this basin
#pragma unroll
        for (int off = 8; off; off >>= 1)
            p += __shfl_xor_sync(0xffffffffu, p, off, 16);
        if (h == 0) out[idx] = p;
    }
}

// ============================================================================
// launch
// ============================================================================
extern "C" void kernel_launch(void* const* d_in, const int* in_sizes, int n_in,
                              void* d_out, int out_size)
{
    const float* x       = (const float*)d_in[0];
    const float* xc      = (const float*)d_in[1];
    const float* fc_W1   = (const float*)d_in[2];
    const float* fc_b1   = (const float*)d_in[3];
    const float* fc_W2   = (const float*)d_in[4];
    const float* fc_b2   = (const float*)d_in[5];
    const float* fcR_W1  = (const float*)d_in[6];
    const float* fcR_b1  = (const float*)d_in[7];
    const float* fcR_W2  = (const float*)d_in[8];
    const float* fcR_b2  = (const float*)d_in[9];
    const float* fcT1_W1 = (const float*)d_in[10];
    const float* fcT1_b1 = (const float*)d_in[11];
    const float* fcT1_W2 = (const float*)d_in[12];
    const float* fcT1_b2 = (const float*)d_in[13];
    const float* fcT2_W1 = (const float*)d_in[14];
    const float* fcT2_b1 = (const float*)d_in[15];
    const float* fcT2_W2 = (const float*)d_in[16];
    const float* fcT2_b2 = (const float*)d_in[17];
    float* out = (float*)d_out;

    cudaFuncSetAttribute(k_mlp, cudaFuncAttributeMaxDynamicSharedMemorySize, K2_SMEM_BYTES);

    k_hidden<<<NS_ / 8, 256>>>(xc, fc_W1, fc_b1, fcR_W1, fcR_b1,
                               fcT1_W1, fcT1_b1, fcT2_W1, fcT2_b1);
    k_outputs<<<NS_ / 8, 256>>>(fc_W2, fc_b2, fcR_W2, fcR_b2);
    k_mlp<<<dim3(NS_, 3), 256, K2_SMEM_BYTES>>>(x, fcT1_W1, fcT1_W2, fcT1_b2,
                                                fcT2_W1, fcT2_W2, fcT2_b2);
    k_scan<<<(NS_ * NH_) / 256, 256>>>(x, out);
}

// round 6
// speedup vs baseline: 1.1987x; 1.1987x over previous
#include <cuda_runtime.h>
#include <cuda_bf16.h>
#include <math.h>

// Problem dims
#define NT_ 730
#define NS_ 2000
#define NH_ 16
#define NG_ 32
#define NR_ 15

// ---------------- scratch (device globals; no allocations allowed) ----------------
__device__ float g_hfc [NS_ * 256];          // tanh hidden of fc
__device__ float g_hR  [NS_ * 256];          // tanh hidden of fcR
__device__ float g_base1[NS_ * 256];         // fcT1 layer1 basin-constant preact (incl bias)
__device__ float g_base2[NS_ * 256];         // fcT2 layer1 basin-constant preact (incl bias)
__device__ float g_params[8][NS_ * NH_];     // k1,k2,k23,k3,gl,qb,ge1,ge2  [p][s*16+h]
__device__ float g_rr  [NS_ * NH_ * 16];     // ga*relu(wR) taps, lag-indexed, padded to 16
// fused per-lane scan inputs: {Pl1, Pl2, vk, vm}; +2 t-planes of padding for prefetch
__device__ float4 g_v4 [(NT_ + 2) * NS_ * NH_];
// per-(t,s): {Ps, E}; +2 t-planes padding
__device__ float2 g_pe [(NT_ + 2) * NS_];

// ---------------- helpers ----------------
__device__ __forceinline__ float tanh_hw(float x) {
    float y;
    asm("tanh.approx.f32 %0, %1;" : "=f"(y) : "f"(x));
    return y;
}
__device__ __forceinline__ float rcp_fast(float x) {
    float y;
    asm("rcp.approx.f32 %0, %1;" : "=f"(y) : "f"(x));
    return y;
}
// accurate-ish tanh for the vm path: 1 - 2/(e^{2x}+1)
__device__ __forceinline__ float tanh_acc(float x) {
    float z = fminf(x, 8.f);               // pos clamp only; neg side underflows safely
    float e = __expf(z + z);
    return fmaf(-2.f, rcp_fast(e + 1.f), 1.f);
}

__device__ __forceinline__ void unpack2(unsigned long long v, float& a, float& b) {
    unsigned int lo, hi;
    asm("mov.b64 {%0, %1}, %2;" : "=r"(lo), "=r"(hi) : "l"(v));
    a = __uint_as_float(lo);
    b = __uint_as_float(hi);
}
__device__ __forceinline__ unsigned long long pack2s(float a) {
    unsigned long long r;
    asm("mov.b64 %0, {%1, %1};" : "=l"(r) : "r"(__float_as_uint(a)));
    return r;
}
__device__ __forceinline__ void fma2(unsigned long long& d, unsigned long long a, unsigned long long b) {
    asm("fma.rn.f32x2 %0, %1, %2, %0;" : "+l"(d) : "l"(a), "l"(b));
}

// ============================================================================
// Kernel 1a: per-basin hidden activations + time-invariant layer-1 bases
// ============================================================================
__global__ void __launch_bounds__(256) k_hidden(
    const float* __restrict__ xc,
    const float* __restrict__ fc_W1,  const float* __restrict__ fc_b1,
    const float* __restrict__ fcR_W1, const float* __restrict__ fcR_b1,
    const float* __restrict__ fcT1_W1, const float* __restrict__ fcT1_b1,
    const float* __restrict__ fcT2_W1, const float* __restrict__ fcT2_b1)
{
    __shared__ float xcs[8][NG_];
    const int tid = threadIdx.x;
    const int s0  = blockIdx.x * 8;
    xcs[tid >> 5][tid & 31] = xc[s0 * NG_ + tid];
    __syncthreads();

    const int j = tid;
    float acc[8];

    {
        float b = fc_b1[j];
#pragma unroll
        for (int i = 0; i < 8; i++) acc[i] = b;
        const float4* row = (const float4*)(fc_W1 + j * NG_);
#pragma unroll
        for (int q = 0; q < 8; q++) {
            float4 w = row[q];
#pragma unroll
            for (int i = 0; i < 8; i++) {
                acc[i] = fmaf(w.x, xcs[i][4*q+0], acc[i]);
                acc[i] = fmaf(w.y, xcs[i][4*q+1], acc[i]);
                acc[i] = fmaf(w.z, xcs[i][4*q+2], acc[i]);
                acc[i] = fmaf(w.w, xcs[i][4*q+3], acc[i]);
            }
        }
#pragma unroll
        for (int i = 0; i < 8; i++) g_hfc[(s0 + i) * 256 + j] = tanhf(acc[i]);
    }
    {
        float b = fcR_b1[j];
#pragma unroll
        for (int i = 0; i < 8; i++) acc[i] = b;
        const float4* row = (const float4*)(fcR_W1 + j * NG_);
#pragma unroll
        for (int q = 0; q < 8; q++) {
            float4 w = row[q];
#pragma unroll
            for (int i = 0; i < 8; i++) {
                acc[i] = fmaf(w.x, xcs[i][4*q+0], acc[i]);
                acc[i] = fmaf(w.y, xcs[i][4*q+1], acc[i]);
                acc[i] = fmaf(w.z, xcs[i][4*q+2], acc[i]);
                acc[i] = fmaf(w.w, xcs[i][4*q+3], acc[i]);
            }
        }
#pragma unroll
        for (int i = 0; i < 8; i++) g_hR[(s0 + i) * 256 + j] = tanhf(acc[i]);
    }
    {
        float b = fcT1_b1[j];
#pragma unroll
        for (int i = 0; i < 8; i++) acc[i] = b;
        const float* row = fcT1_W1 + j * 33 + 1;
#pragma unroll
        for (int g = 0; g < NG_; g++) {
            float w = row[g];
#pragma unroll
            for (int i = 0; i < 8; i++) acc[i] = fmaf(w, xcs[i][g], acc[i]);
        }
#pragma unroll
        for (int i = 0; i < 8; i++) g_base1[(s0 + i) * 256 + j] = acc[i];
    }
    {
        float b = fcT2_b1[j];
#pragma unroll
        for (int i = 0; i < 8; i++) acc[i] = b;
        const float* row = fcT2_W1 + j * 35 + 3;
#pragma unroll
        for (int g = 0; g < NG_; g++) {
            float w = row[g];
#pragma unroll
            for (int i = 0; i < 8; i++) acc[i] = fmaf(w, xcs[i][g], acc[i]);
        }
#pragma unroll
        for (int i = 0; i < 8; i++) g_base2[(s0 + i) * 256 + j] = acc[i];
    }
}

// ============================================================================
// Kernel 1b: per-basin output layers -> scan params + routing taps
// ============================================================================
__global__ void __launch_bounds__(256) k_outputs(
    const float* __restrict__ fc_W2,  const float* __restrict__ fc_b2,
    const float* __restrict__ fcR_W2, const float* __restrict__ fcR_b2)
{
    __shared__ float hf[8][256];
    __shared__ float hr[8][256];
    __shared__ float w8[8][160];
    __shared__ float r8[8][240];
    __shared__ float ga8[8][NH_];

    const int tid = threadIdx.x;
    const int s0  = blockIdx.x * 8;

    for (int idx = tid; idx < 2048; idx += 256) {
        int b = idx >> 8, j = idx & 255;
        hf[b][j] = g_hfc[(s0 + b) * 256 + j];
        hr[b][j] = g_hR [(s0 + b) * 256 + j];
    }
    __syncthreads();

    if (tid < 160) {
        const int o = tid;
        float acc[8];
        float bb = fc_b2[o];
#pragma unroll
        for (int i = 0; i < 8; i++) acc[i] = bb;
        const float4* row = (const float4*)(fc_W2 + o * 256);
        for (int q = 0; q < 64; q++) {
            float4 w = row[q];
#pragma unroll
            for (int i = 0; i < 8; i++) {
                acc[i] = fmaf(w.x, hf[i][4*q+0], acc[i]);
                acc[i] = fmaf(w.y, hf[i][4*q+1], acc[i]);
                acc[i] = fmaf(w.z, hf[i][4*q+2], acc[i]);
                acc[i] = fmaf(w.w, hf[i][4*q+3], acc[i]);
            }
        }
#pragma unroll
        for (int i = 0; i < 8; i++) w8[i][o] = acc[i];
    }
    if (tid < 240) {
        const int o = tid;
        float acc[8];
        float bb = fcR_b2[o];
#pragma unroll
        for (int i = 0; i < 8; i++) acc[i] = bb;
        const float4* row = (const float4*)(fcR_W2 + o * 256);
        for (int q = 0; q < 64; q++) {
            float4 w = row[q];
#pragma unroll
            for (int i = 0; i < 8; i++) {
                acc[i] = fmaf(w.x, hr[i][4*q+0], acc[i]);
                acc[i] = fmaf(w.y, hr[i][4*q+1], acc[i]);
                acc[i] = fmaf(w.z, hr[i][4*q+2], acc[i]);
                acc[i] = fmaf(w.w, hr[i][4*q+3], acc[i]);
            }
        }
#pragma unroll
        for (int i = 0; i < 8; i++) r8[i][o] = fmaxf(acc[i], 0.f);
    }
    __syncthreads();

    if (tid < 128) {
        const int b = tid >> 4, h = tid & 15;
        const float* wb = w8[b];
        float k1  = 1.f / (1.f + expf(-wb[16  + h]));
        float k2  = 1.f / (1.f + expf(-wb[32  + h]));
        float k23 = 1.f / (1.f + expf(-wb[48  + h]));
        float k3  = (1.f / (1.f + expf(-wb[64 + h]))) * 0.1f;
        float gl  = expf(wb[80 + h]) * 2.f;
        float qb  = fmaxf(wb[112 + h], 0.f);
        float ge1 = fmaxf(wb[128 + h], 0.f);
        float ge2 = fmaxf(wb[144 + h], 0.f);
        float m = wb[96];
        for (int i = 1; i < 16; i++) m = fmaxf(m, wb[96 + i]);
        float sum = 0.f;
        for (int i = 0; i < 16; i++) sum += expf(wb[96 + i] - m);
        float ga = expf(wb[96 + h] - m) / sum;
        ga8[b][h] = ga;

        const int lane = (s0 + b) * NH_ + h;
        g_params[0][lane] = k1;
        g_params[1][lane] = k2;
        g_params[2][lane] = k23;
        g_params[3][lane] = k3;
        g_params[4][lane] = gl;
        g_params[5][lane] = qb;
        g_params[6][lane] = ge1;
        g_params[7][lane] = ge2;
        g_rr[lane * 16 + 15] = 0.f;
    }
    __syncthreads();

    for (int idx = tid; idx < 8 * 240; idx += 256) {
        int b = idx / 240, o = idx % 240;
        int h = o / NR_, jj = o % NR_;
        int lane = (s0 + b) * NH_ + h;
        g_rr[lane * 16 + (14 - jj)] = ga8[b][h] * r8[b][o];
    }
}

// ============================================================================
// Kernel 2: per-(t,s) MLPs -> fused scan inputs {Pl1,Pl2,vk,vm} + {Ps,E}
// block = (basin s, 256 timesteps); FFMA2-packed layer-2
// ============================================================================
#define K2_SMEM_FLOATS (256 * 48 + 256 * 8 + 48 + 256 * 6)
#define K2_SMEM_BYTES  (K2_SMEM_FLOATS * 4)

__global__ void __launch_bounds__(256) k_mlp(
    const float* __restrict__ x,
    const float* __restrict__ fcT1_W1, const float* __restrict__ fcT1_W2,
    const float* __restrict__ fcT1_b2,
    const float* __restrict__ fcT2_W1, const float* __restrict__ fcT2_W2,
    const float* __restrict__ fcT2_b2)
{
    extern __shared__ float sm[];
    float* W_sm  = sm;                       // [256][48]
    float* coef  = sm + 256 * 48;            // [256][8]
    float* biasS = coef + 256 * 8;           // [48]
    float* xs    = biasS + 48;               // [256][6] staged forcings

    const int tid = threadIdx.x;
    const int s   = blockIdx.x;
    const int t0  = blockIdx.y << 8;

    for (int idx = tid; idx < 32 * 256; idx += 256) {
        int k = idx >> 8, j = idx & 255;
        W_sm[j * 48 + k] = fcT1_W2[idx];
    }
    for (int idx = tid; idx < 16 * 256; idx += 256) {
        int k = idx >> 8, j = idx & 255;
        W_sm[j * 48 + 32 + k] = fcT2_W2[idx];
    }
    {
        int j = tid;
        float* c = coef + j * 8;
        c[0] = g_base1[s * 256 + j];
        c[1] = fcT1_W1[j * 33];        // LAI coefficient
        c[2] = g_base2[s * 256 + j];
        c[3] = fcT2_W1[j * 35 + 0];    // R
        c[4] = fcT2_W1[j * 35 + 1];    // T1
        c[5] = fcT2_W1[j * 35 + 2];    // T2
        c[6] = 0.f; c[7] = 0.f;
    }
    if (tid < 32) biasS[tid]      = fcT1_b2[tid];
    if (tid < 16) biasS[32 + tid] = fcT2_b2[tid];
    // cooperative coalesced stage of x[t0..t0+255, s, 0..5]
    for (int idx = tid; idx < 256 * 6; idx += 256) {
        int tl = idx / 6, c = idx % 6;
        int t  = t0 + tl;
        xs[idx] = (t < NT_) ? x[((size_t)t * NS_ + s) * 6 + c] : 0.f;
    }
    __syncthreads();

    const int t = t0 + tid;
    const bool act = (t < NT_);
    const float P   = xs[tid * 6 + 0];
    const float E   = xs[tid * 6 + 1];
    const float Ta  = xs[tid * 6 + 2];
    const float Tb  = xs[tid * 6 + 3];
    const float Rv  = xs[tid * 6 + 4];
    const float LAI = xs[tid * 6 + 5];

    // snow/rain partition vp (paid once per (t,s) here, not per-h in the scan)
    float den = Tb - Ta;
    float ra  = (Ta + Tb) / (den == 0.f ? 1.f : den);
    ra = fminf(fmaxf(ra, -1.f), 1.f);
    if (Ta >= 0.f || Tb <= 0.f) ra = 0.f;
    float vp = 1.f - acosf(ra) * (1.f / 3.1415f);
    if (Ta >= 0.f) vp = 1.f;
    if (Tb <= 0.f) vp = 0.f;
    const float Ps = P * (1.f - vp);
    const float Pl = P * vp;

    unsigned long long acc[24];
#pragma unroll
    for (int i = 0; i < 24; i++) acc[i] = 0ULL;

#pragma unroll 2
    for (int j = 0; j < 256; j++) {
        const float4* c4 = (const float4*)(coef + j * 8);
        float4 cA = c4[0];
        float4 cB = c4[1];
        float h1 = tanh_hw(fmaf(LAI, cA.y, cA.x));
        float p2 = fmaf(Rv, cA.w, cA.z);
        p2 = fmaf(Ta, cB.x, p2);
        p2 = fmaf(Tb, cB.y, p2);
        float h2 = tanh_acc(p2);
        unsigned long long hh1 = pack2s(h1);
        unsigned long long hh2 = pack2s(h2);
        const ulonglong2* wrow = (const ulonglong2*)(W_sm + j * 48);
#pragma unroll
        for (int q = 0; q < 8; q++) {
            ulonglong2 wv = wrow[q];
            fma2(acc[2*q + 0], wv.x, hh1);
            fma2(acc[2*q + 1], wv.y, hh1);
        }
#pragma unroll
        for (int q = 8; q < 12; q++) {
            ulonglong2 wv = wrow[q];
            fma2(acc[2*q + 0], wv.x, hh2);
            fma2(acc[2*q + 1], wv.y, hh2);
        }
    }

    if (act) {
        float o[48];
#pragma unroll
        for (int p = 0; p < 24; p++) unpack2(acc[p], o[2*p], o[2*p + 1]);

        float4* dst = g_v4 + ((size_t)t * NS_ + s) * NH_;
        const float inv6 = 1.f / 6.f;
#pragma unroll
        for (int h = 0; h < NH_; h++) {
            float vi = __saturatef(fmaf(o[h]      + biasS[h],      inv6, 0.5f));
            float vk = __saturatef(fmaf(o[16 + h] + biasS[16 + h], inv6, 0.5f));
            float vm = __expf(2.f * (o[32 + h] + biasS[32 + h]));
            float Pl2 = Pl * vi;
            float4 v;
            v.x = Pl - Pl2;   // Pl1
            v.y = Pl2;
            v.z = vk;
            v.w = vm;
            __stcs(dst + h, v);
        }
        float2 pe; pe.x = Ps; pe.y = E;
        __stcs(g_pe + (size_t)t * NS_ + s, pe);
    }
}

// ============================================================================
// Kernel 3: sequential scan, fused causal routing conv + h-reduction.
// One thread per (s,h); t-loop unrolled by 14 (ring period) -> static ring;
// depth-2 register prefetch of the streaming inputs.
// ============================================================================
__global__ void __launch_bounds__(128) k_scan(float* __restrict__ out)
{
    const int lane = blockIdx.x * 128 + threadIdx.x;   // 0..31999
    const int s = lane >> 4;
    const int h = lane & 15;

    const float k1  = g_params[0][lane];
    const float k2  = g_params[1][lane];
    const float k23 = g_params[2][lane];
    const float k3  = g_params[3][lane];
    const float gl  = g_params[4][lane];
    const float qb  = g_params[5][lane];
    const float ge1 = g_params[6][lane];
    const float ge2 = g_params[7][lane];
    const float c23 = 1.f - k23;

    float rr[15];
#pragma unroll
    for (int d = 0; d < 15; d++) rr[d] = g_rr[lane * 16 + d];

    float ring[14];
#pragma unroll
    for (int d = 0; d < 14; d++) ring[d] = 0.f;

    float S0 = 0.f, Sv = 0.f, S2 = 0.f, S3 = 0.f;

    // depth-2 prefetch streams (arrays are padded by 2 t-planes)
    const float4* pv = g_v4 + (size_t)s * NH_ + h;
    const float2* pp = g_pe + s;
    float4 va = __ldcs(pv);
    float4 vb = __ldcs(pv + (size_t)NS_ * NH_);
    float2 pa = __ldcs(pp);
    float2 pb = __ldcs(pp + NS_);
    pv += (size_t)2 * NS_ * NH_;
    pp += 2 * NS_;

#define SCAN_BODY(T, U)                                                        \
    {                                                                          \
        float4 v = va; va = vb; vb = __ldcs(pv); pv += (size_t)NS_ * NH_;      \
        float2 pe = pa; pa = pb; pb = __ldcs(pp); pp += NS_;                   \
        float Ev1 = pe.y * ge1;                                                \
        float Ev2 = pe.y * ge2;                                                \
        float H0  = S0 + pe.x;                                                 \
        float qSm = fminf(H0, v.w);                                            \
        float Hv  = fmaxf(Sv + v.x - Ev1, 0.f);                                \
        float qv  = Sv * v.z;                                                  \
        float H2  = fmaxf(S2 + qSm + qv - Ev2 + v.y, 0.f);                     \
        float x1  = H2 - gl;                                                   \
        float Q1  = (x1 > 0.f) ? __powf(x1, k1) : 0.f;                         \
        float q2  = fminf(H2, gl) * k2;                                        \
        float Q2  = q2 * c23;                                                  \
        float H3  = fmaf(q2, k23, S3);                                         \
        float Q3  = fmaf(H3, k3, qb);                                          \
        S0 = H0 - qSm;                                                         \
        Sv = Hv - qv;                                                          \
        S2 = H2 - Q1 - q2;                                                     \
        S3 = H3 - Q3;                                                          \
        float Qs = Q1 + Q2 + Q3;                                               \
        float p = rr[0] * Qs;                                                  \
        _Pragma("unroll")                                                      \
        for (int d = 1; d < 15; d++)                                           \
            p = fmaf(rr[d], ring[((U) - d + 28) % 14], p);                     \
        ring[(U)] = Qs;                                                        \
        _Pragma("unroll")                                                      \
        for (int off = 8; off; off >>= 1)                                      \
            p += __shfl_xor_sync(0xffffffffu, p, off, 16);                     \
        if (h == 0) out[(size_t)(T) * NS_ + s] = p;                            \
    }

#pragma unroll 1
    for (int tb = 0; tb < 728; tb += 14) {
#pragma unroll
        for (int u = 0; u < 14; u++) {
            SCAN_BODY(tb + u, u)
        }
    }
    // 728 == 52*14, so the ring phase continues with u = 0, 1
    SCAN_BODY(728, 0)
    SCAN_BODY(729, 1)
#undef SCAN_BODY
}

// ============================================================================
// launch
// ============================================================================
extern "C" void kernel_launch(void* const* d_in, const int* in_sizes, int n_in,
                              void* d_out, int out_size)
{
    const float* x       = (const float*)d_in[0];
    const float* xc      = (const float*)d_in[1];
    const float* fc_W1   = (const float*)d_in[2];
    const float* fc_b1   = (const float*)d_in[3];
    const float* fc_W2   = (const float*)d_in[4];
    const float* fc_b2   = (const float*)d_in[5];
    const float* fcR_W1  = (const float*)d_in[6];
    const float* fcR_b1  = (const float*)d_in[7];
    const float* fcR_W2  = (const float*)d_in[8];
    const float* fcR_b2  = (const float*)d_in[9];
    const float* fcT1_W1 = (const float*)d_in[10];
    const float* fcT1_b1 = (const float*)d_in[11];
    const float* fcT1_W2 = (const float*)d_in[12];
    const float* fcT1_b2 = (const float*)d_in[13];
    const float* fcT2_W1 = (const float*)d_in[14];
    const float* fcT2_b1 = (const float*)d_in[15];
    const float* fcT2_W2 = (const float*)d_in[16];
    const float* fcT2_b2 = (const float*)d_in[17];
    float* out = (float*)d_out;

    cudaFuncSetAttribute(k_mlp, cudaFuncAttributeMaxDynamicSharedMemorySize, K2_SMEM_BYTES);

    k_hidden<<<NS_ / 8, 256>>>(xc, fc_W1, fc_b1, fcR_W1, fcR_b1,
                               fcT1_W1, fcT1_b1, fcT2_W1, fcT2_b1);
    k_outputs<<<NS_ / 8, 256>>>(fc_W2, fc_b2, fcR_W2, fcR_b2);
    k_mlp<<<dim3(NS_, 3), 256, K2_SMEM_BYTES>>>(x, fcT1_W1, fcT1_W2, fcT1_b2,
                                                fcT2_W1, fcT2_W2, fcT2_b2);
    k_scan<<<(NS_ * NH_) / 128, 128>>>(out);
}

// round 10
// speedup vs baseline: 1.8946x; 1.5806x over previous
#include <cuda_runtime.h>
#include <cuda_bf16.h>
#include <math.h>

// Problem dims
#define NT_ 730
#define NS_ 2000
#define NH_ 16
#define NG_ 32
#define NR_ 15

// ---------------- scratch (device globals; no allocations allowed) ----------------
__device__ float g_hfc [NS_ * 256];
__device__ float g_hR  [NS_ * 256];
__device__ float g_base1[NS_ * 256];
__device__ float g_base2[NS_ * 256];
__device__ float g_params[8][NS_ * NH_];
__device__ float g_rr  [NS_ * NH_ * 16];          // ga*relu(wR) taps, lag-indexed
__device__ uint2  g_PW  [6144];                   // W frag-packed, tf32 bits
__device__ float  g_c1  [256];                    // fcT1_W1 LAI col
__device__ float4 g_dvec[256];                    // fcT2_W1 {R,T1,T2} cols
__device__ float  g_bias48[48];
// fused per-lane scan inputs: {Pl1, Pl2, vk, vm}; +4 t-planes pad for prefetch
__device__ float4 g_v4 [(NT_ + 4) * NS_ * NH_];
__device__ float2 g_pe [(NT_ + 4) * NS_];         // per-(t,s): {Ps, E}
__device__ float  g_Qs [NT_ * NS_ * NH_];         // per-lane Q1+Q2+Q3

// ---------------- helpers ----------------
__device__ __forceinline__ float tanh_hw(float x) {
    float y;
    asm("tanh.approx.f32 %0, %1;" : "=f"(y) : "f"(x));
    return y;
}
__device__ __forceinline__ unsigned cvt_tf32(float f) {
    unsigned u;
    asm("cvt.rna.tf32.f32 %0, %1;" : "=r"(u) : "f"(f));
    return u;
}
#define MMA_TF32(D, a0, a1, a2, a3, b0, b1)                                   \
    asm("mma.sync.aligned.m16n8k8.row.col.f32.tf32.tf32.f32 "                 \
        "{%0,%1,%2,%3}, {%4,%5,%6,%7}, {%8,%9}, {%0,%1,%2,%3};"               \
        : "+f"((D)[0]), "+f"((D)[1]), "+f"((D)[2]), "+f"((D)[3])              \
        : "r"(a0), "r"(a1), "r"(a2), "r"(a3), "r"(b0), "r"(b1))

// ============================================================================
// Kernel 1a: per-basin hidden activations + time-invariant layer-1 bases
// ============================================================================
__global__ void __launch_bounds__(256) k_hidden(
    const float* __restrict__ xc,
    const float* __restrict__ fc_W1,  const float* __restrict__ fc_b1,
    const float* __restrict__ fcR_W1, const float* __restrict__ fcR_b1,
    const float* __restrict__ fcT1_W1, const float* __restrict__ fcT1_b1,
    const float* __restrict__ fcT2_W1, const float* __restrict__ fcT2_b1)
{
    __shared__ float xcs[8][NG_];
    const int tid = threadIdx.x;
    const int s0  = blockIdx.x * 8;
    xcs[tid >> 5][tid & 31] = xc[s0 * NG_ + tid];
    __syncthreads();

    const int j = tid;
    float acc[8];

    {
        float b = fc_b1[j];
#pragma unroll
        for (int i = 0; i < 8; i++) acc[i] = b;
        const float4* row = (const float4*)(fc_W1 + j * NG_);
#pragma unroll
        for (int q = 0; q < 8; q++) {
            float4 w = row[q];
#pragma unroll
            for (int i = 0; i < 8; i++) {
                acc[i] = fmaf(w.x, xcs[i][4*q+0], acc[i]);
                acc[i] = fmaf(w.y, xcs[i][4*q+1], acc[i]);
                acc[i] = fmaf(w.z, xcs[i][4*q+2], acc[i]);
                acc[i] = fmaf(w.w, xcs[i][4*q+3], acc[i]);
            }
        }
#pragma unroll
        for (int i = 0; i < 8; i++) g_hfc[(s0 + i) * 256 + j] = tanhf(acc[i]);
    }
    {
        float b = fcR_b1[j];
#pragma unroll
        for (int i = 0; i < 8; i++) acc[i] = b;
        const float4* row = (const float4*)(fcR_W1 + j * NG_);
#pragma unroll
        for (int q = 0; q < 8; q++) {
            float4 w = row[q];
#pragma unroll
            for (int i = 0; i < 8; i++) {
                acc[i] = fmaf(w.x, xcs[i][4*q+0], acc[i]);
                acc[i] = fmaf(w.y, xcs[i][4*q+1], acc[i]);
                acc[i] = fmaf(w.z, xcs[i][4*q+2], acc[i]);
                acc[i] = fmaf(w.w, xcs[i][4*q+3], acc[i]);
            }
        }
#pragma unroll
        for (int i = 0; i < 8; i++) g_hR[(s0 + i) * 256 + j] = tanhf(acc[i]);
    }
    {
        float b = fcT1_b1[j];
#pragma unroll
        for (int i = 0; i < 8; i++) acc[i] = b;
        const float* row = fcT1_W1 + j * 33 + 1;
#pragma unroll
        for (int g = 0; g < NG_; g++) {
            float w = row[g];
#pragma unroll
            for (int i = 0; i < 8; i++) acc[i] = fmaf(w, xcs[i][g], acc[i]);
        }
#pragma unroll
        for (int i = 0; i < 8; i++) g_base1[(s0 + i) * 256 + j] = acc[i];
    }
    {
        float b = fcT2_b1[j];
#pragma unroll
        for (int i = 0; i < 8; i++) acc[i] = b;
        const float* row = fcT2_W1 + j * 35 + 3;
#pragma unroll
        for (int g = 0; g < NG_; g++) {
            float w = row[g];
#pragma unroll
            for (int i = 0; i < 8; i++) acc[i] = fmaf(w, xcs[i][g], acc[i]);
        }
#pragma unroll
        for (int i = 0; i < 8; i++) g_base2[(s0 + i) * 256 + j] = acc[i];
    }
}

// ============================================================================
// Kernel 1b: per-basin output layers -> scan params + routing taps
// ============================================================================
__global__ void __launch_bounds__(256) k_outputs(
    const float* __restrict__ fc_W2,  const float* __restrict__ fc_b2,
    const float* __restrict__ fcR_W2, const float* __restrict__ fcR_b2)
{
    __shared__ float hf[8][256];
    __shared__ float hr[8][256];
    __shared__ float w8[8][160];
    __shared__ float r8[8][240];
    __shared__ float ga8[8][NH_];

    const int tid = threadIdx.x;
    const int s0  = blockIdx.x * 8;

    for (int idx = tid; idx < 2048; idx += 256) {
        int b = idx >> 8, j = idx & 255;
        hf[b][j] = g_hfc[(s0 + b) * 256 + j];
        hr[b][j] = g_hR [(s0 + b) * 256 + j];
    }
    __syncthreads();

    if (tid < 160) {
        const int o = tid;
        float acc[8];
        float bb = fc_b2[o];
#pragma unroll
        for (int i = 0; i < 8; i++) acc[i] = bb;
        const float4* row = (const float4*)(fc_W2 + o * 256);
        for (int q = 0; q < 64; q++) {
            float4 w = row[q];
#pragma unroll
            for (int i = 0; i < 8; i++) {
                acc[i] = fmaf(w.x, hf[i][4*q+0], acc[i]);
                acc[i] = fmaf(w.y, hf[i][4*q+1], acc[i]);
                acc[i] = fmaf(w.z, hf[i][4*q+2], acc[i]);
                acc[i] = fmaf(w.w, hf[i][4*q+3], acc[i]);
            }
        }
#pragma unroll
        for (int i = 0; i < 8; i++) w8[i][o] = acc[i];
    }
    if (tid < 240) {
        const int o = tid;
        float acc[8];
        float bb = fcR_b2[o];
#pragma unroll
        for (int i = 0; i < 8; i++) acc[i] = bb;
        const float4* row = (const float4*)(fcR_W2 + o * 256);
        for (int q = 0; q < 64; q++) {
            float4 w = row[q];
#pragma unroll
            for (int i = 0; i < 8; i++) {
                acc[i] = fmaf(w.x, hr[i][4*q+0], acc[i]);
                acc[i] = fmaf(w.y, hr[i][4*q+1], acc[i]);
                acc[i] = fmaf(w.z, hr[i][4*q+2], acc[i]);
                acc[i] = fmaf(w.w, hr[i][4*q+3], acc[i]);
            }
        }
#pragma unroll
        for (int i = 0; i < 8; i++) r8[i][o] = fmaxf(acc[i], 0.f);
    }
    __syncthreads();

    if (tid < 128) {
        const int b = tid >> 4, h = tid & 15;
        const float* wb = w8[b];
        float k1  = 1.f / (1.f + expf(-wb[16  + h]));
        float k2  = 1.f / (1.f + expf(-wb[32  + h]));
        float k23 = 1.f / (1.f + expf(-wb[48  + h]));
        float k3  = (1.f / (1.f + expf(-wb[64 + h]))) * 0.1f;
        float gl  = expf(wb[80 + h]) * 2.f;
        float qb  = fmaxf(wb[112 + h], 0.f);
        float ge1 = fmaxf(wb[128 + h], 0.f);
        float ge2 = fmaxf(wb[144 + h], 0.f);
        float m = wb[96];
        for (int i = 1; i < 16; i++) m = fmaxf(m, wb[96 + i]);
        float sum = 0.f;
        for (int i = 0; i < 16; i++) sum += expf(wb[96 + i] - m);
        float ga = expf(wb[96 + h] - m) / sum;
        ga8[b][h] = ga;

        const int lane = (s0 + b) * NH_ + h;
        g_params[0][lane] = k1;
        g_params[1][lane] = k2;
        g_params[2][lane] = k23;
        g_params[3][lane] = k3;
        g_params[4][lane] = gl;
        g_params[5][lane] = qb;
        g_params[6][lane] = ge1;
        g_params[7][lane] = ge2;
        g_rr[lane * 16 + 15] = 0.f;
    }
    __syncthreads();

    for (int idx = tid; idx < 8 * 240; idx += 256) {
        int b = idx / 240, o = idx % 240;
        int h = o / NR_, jj = o % NR_;
        int lane = (s0 + b) * NH_ + h;
        g_rr[lane * 16 + (14 - jj)] = ga8[b][h] * r8[b][o];
    }
}

// ============================================================================
// Kernel 1c: pack layer-2 weights into mma B-fragment layout (tf32 bits),
// plus dynamic-input layer-1 columns and output biases.
// grid 24 x 256 = 6144 threads
// ============================================================================
__global__ void __launch_bounds__(256) k_prep(
    const float* __restrict__ fcT1_W1, const float* __restrict__ fcT1_W2,
    const float* __restrict__ fcT1_b2,
    const float* __restrict__ fcT2_W1, const float* __restrict__ fcT2_W2,
    const float* __restrict__ fcT2_b2)
{
    const int idx = blockIdx.x * 256 + threadIdx.x;   // 0..6143
    {
        const int kk   = idx / 192;
        const int rem  = idx % 192;
        const int nt   = rem / 32;
        const int lane = rem % 32;
        const int j    = kk * 8 + (lane & 3);
        const int oo   = lane >> 2;
        float w0, w1;
        if (nt < 4) {
            int o = nt * 8 + oo;
            w0 = fcT1_W2[o * 256 + j];
            w1 = fcT1_W2[o * 256 + j + 4];
        } else {
            int o = (nt - 4) * 8 + oo;
            w0 = fcT2_W2[o * 256 + j];
            w1 = fcT2_W2[o * 256 + j + 4];
        }
        uint2 u;
        u.x = cvt_tf32(w0);
        u.y = cvt_tf32(w1);
        g_PW[idx] = u;
    }
    if (idx < 256) {
        g_c1[idx] = fcT1_W1[idx * 33];
        float4 dv;
        dv.x = fcT2_W1[idx * 35 + 0];
        dv.y = fcT2_W1[idx * 35 + 1];
        dv.z = fcT2_W1[idx * 35 + 2];
        dv.w = 0.f;
        g_dvec[idx] = dv;
    }
    if (idx < 48) g_bias48[idx] = (idx < 32) ? fcT1_b2[idx] : fcT2_b2[idx - 32];
}

// ============================================================================
// Kernel 2: tensor-core per-(t,s) MLPs -> {Pl1,Pl2,vk,vm} + {Ps,E}
// block = (basin s, 128 timesteps), 4 warps; tf32 m16n8k8 mma
// ============================================================================
#define KM_SMEM_FLOATS 21296
#define KM_SMEM_BYTES  (KM_SMEM_FLOATS * 4)

__global__ void __launch_bounds__(128) k_mlp_tc(const float* __restrict__ x)
{
    extern __shared__ float sm[];
    float4* sdvec  = (float4*)sm;               // [256]
    float*  sD     = sm + 1024;                 // [128][50]
    uint2*  sPW    = (uint2*)(sm + 7424);       // [6144]
    float2* scoef1 = (float2*)(sm + 19712);     // [256] {base1, c1}
    float*  sxs    = sm + 20224;                // [128][6]
    float*  sbase2 = sm + 20992;                // [256]
    float*  sbias  = sm + 21248;                // [48]

    const int tid = threadIdx.x;
    const int s   = blockIdx.x;
    const int t0  = blockIdx.y << 7;

    for (int i = tid; i < 6144; i += 128) sPW[i] = g_PW[i];
    for (int i = tid; i < 256; i += 128) {
        scoef1[i] = make_float2(g_base1[s * 256 + i], g_c1[i]);
        sbase2[i] = g_base2[s * 256 + i];
        sdvec[i]  = g_dvec[i];
    }
    if (tid < 48) sbias[tid] = g_bias48[tid];
    for (int i = tid; i < 768; i += 128) {
        int tl = i / 6, c = i % 6;
        int t  = t0 + tl;
        sxs[i] = (t < NT_) ? x[((size_t)t * NS_ + s) * 6 + c] : 0.f;
    }
    __syncthreads();

    const int w = tid >> 5, lane = tid & 31;
    const int rq = lane >> 2, qk = lane & 3;
    const int rbase = w * 32 + rq;

    float LAI[4], Rv[4], Ta[4], Tb[4];
#pragma unroll
    for (int i = 0; i < 4; i++) {
        const float* xr = sxs + (rbase + i * 8) * 6;
        Ta[i] = xr[2]; Tb[i] = xr[3]; Rv[i] = xr[4]; LAI[i] = xr[5];
    }

    float dacc[2][6][4];
#pragma unroll
    for (int mt = 0; mt < 2; mt++)
#pragma unroll
        for (int nt = 0; nt < 6; nt++)
#pragma unroll
            for (int r = 0; r < 4; r++) dacc[mt][nt][r] = 0.f;

#pragma unroll 2
    for (int kk = 0; kk < 32; kk++) {
        const int j0 = kk * 8 + qk;
        const uint2* pb = sPW + kk * 192 + lane;

        // ---- G1: h1 = tanh(base1 + LAI*c1), feeds n-tiles 0..3 (vi, vk) ----
        float2 c0  = scoef1[j0];
        float2 c1v = scoef1[j0 + 4];
        unsigned aA[8];
#pragma unroll
        for (int i = 0; i < 4; i++) {
            float hA = tanh_hw(fmaf(LAI[i], c0.y,  c0.x));
            float hB = tanh_hw(fmaf(LAI[i], c1v.y, c1v.x));
            aA[(i >> 1) * 4 + (i & 1)]     = cvt_tf32(hA);
            aA[(i >> 1) * 4 + 2 + (i & 1)] = cvt_tf32(hB);
        }
#pragma unroll
        for (int nt = 0; nt < 4; nt++) {
            uint2 b = pb[nt * 32];
            MMA_TF32(dacc[0][nt], aA[0], aA[1], aA[2], aA[3], b.x, b.y);
            MMA_TF32(dacc[1][nt], aA[4], aA[5], aA[6], aA[7], b.x, b.y);
        }

        // ---- G2: h2 = tanh(base2 + R*d0 + T1*d1 + T2*d2), n-tiles 4..5 (vm) ----
        float  b20 = sbase2[j0], b21 = sbase2[j0 + 4];
        float4 dv0 = sdvec[j0],  dv1 = sdvec[j0 + 4];
        unsigned aB[8];
#pragma unroll
        for (int i = 0; i < 4; i++) {
            float p = fmaf(Rv[i], dv0.x, b20);
            p = fmaf(Ta[i], dv0.y, p);
            p = fmaf(Tb[i], dv0.z, p);
            float hA = tanh_hw(p);
            float q = fmaf(Rv[i], dv1.x, b21);
            q = fmaf(Ta[i], dv1.y, q);
            q = fmaf(Tb[i], dv1.z, q);
            float hB = tanh_hw(q);
            aB[(i >> 1) * 4 + (i & 1)]     = cvt_tf32(hA);
            aB[(i >> 1) * 4 + 2 + (i & 1)] = cvt_tf32(hB);
        }
#pragma unroll
        for (int nt = 4; nt < 6; nt++) {
            uint2 b = pb[nt * 32];
            MMA_TF32(dacc[0][nt], aB[0], aB[1], aB[2], aB[3], b.x, b.y);
            MMA_TF32(dacc[1][nt], aB[4], aB[5], aB[6], aB[7], b.x, b.y);
        }
    }

    // write accumulators to smem [row][col], stride 50
#pragma unroll
    for (int mt = 0; mt < 2; mt++)
#pragma unroll
        for (int nt = 0; nt < 6; nt++) {
            int r = w * 32 + mt * 16 + rq;
            int c = nt * 8 + qk * 2;
            *(float2*)(sD + r * 50 + c)       = make_float2(dacc[mt][nt][0], dacc[mt][nt][1]);
            *(float2*)(sD + (r + 8) * 50 + c) = make_float2(dacc[mt][nt][2], dacc[mt][nt][3]);
        }
    __syncthreads();

    // epilogue: one thread per row (timestep)
    const int t = t0 + tid;
    if (t < NT_) {
        const float* xr = sxs + tid * 6;
        const float P = xr[0], E = xr[1], TaE = xr[2], TbE = xr[3];

        float den = TbE - TaE;
        float ra  = (TaE + TbE) / (den == 0.f ? 1.f : den);
        ra = fminf(fmaxf(ra, -1.f), 1.f);
        if (TaE >= 0.f || TbE <= 0.f) ra = 0.f;
        float vp = 1.f - acosf(ra) * (1.f / 3.1415f);
        if (TaE >= 0.f) vp = 1.f;
        if (TbE <= 0.f) vp = 0.f;
        const float Ps = P * (1.f - vp);
        const float Pl = P * vp;

        const float* Drow = sD + tid * 50;
        float4* dst = g_v4 + (size_t)t * (NS_ * NH_) + s * NH_;
        const float inv6 = 1.f / 6.f;
#pragma unroll
        for (int h = 0; h < NH_; h++) {
            float vi = __saturatef(fmaf(Drow[h]      + sbias[h],      inv6, 0.5f));
            float vk = __saturatef(fmaf(Drow[16 + h] + sbias[16 + h], inv6, 0.5f));
            float vm = __expf(2.f * (Drow[32 + h] + sbias[32 + h]));
            float Pl2 = Pl * vi;
            __stcs(dst + h, make_float4(Pl - Pl2, Pl2, vk, vm));
        }
        float2 pe; pe.x = Ps; pe.y = E;
        __stcs(g_pe + (size_t)t * NS_ + s, pe);
    }
}

// ============================================================================
// Kernel 3: pure recurrence, one thread per (s,h) lane; streams Qs out.
// ============================================================================
__global__ void __launch_bounds__(32) k_scan2()
{
    const int lane = blockIdx.x * 32 + threadIdx.x;   // 0..31999

    const float k1  = g_params[0][lane];
    const float k2  = g_params[1][lane];
    const float k23 = g_params[2][lane];
    const float k3  = g_params[3][lane];
    const float gl  = g_params[4][lane];
    const float qb  = g_params[5][lane];
    const float ge1 = g_params[6][lane];
    const float ge2 = g_params[7][lane];
    const float c23 = 1.f - k23;

    const float4* pv = g_v4 + lane;
    const float2* pp = g_pe + (lane >> 4);
    float4 v0 = __ldcs(pv);
    float4 v1 = __ldcs(pv + NS_ * NH_);
    float4 v2 = __ldcs(pv + 2 * NS_ * NH_);
    float2 q0 = __ldcs(pp);
    float2 q1 = __ldcs(pp + NS_);
    float2 q2r = __ldcs(pp + 2 * NS_);

    float S0 = 0.f, Sv = 0.f, S2 = 0.f, S3 = 0.f;
    float* qout = g_Qs + lane;

#pragma unroll 2
    for (int t = 0; t < NT_; t++) {
        float4 v = v0; v0 = v1; v1 = v2;
        v2 = __ldcs(pv + 3 * NS_ * NH_); pv += NS_ * NH_;
        float2 pe = q0; q0 = q1; q1 = q2r;
        q2r = __ldcs(pp + 3 * NS_); pp += NS_;

        float Ev1 = pe.y * ge1;
        float Ev2 = pe.y * ge2;
        float H0  = S0 + pe.x;
        float qSm = fminf(H0, v.w);
        float Hv  = fmaxf(Sv + v.x - Ev1, 0.f);
        float qv  = Sv * v.z;
        float H2  = fmaxf(S2 + qSm + qv - Ev2 + v.y, 0.f);
        float x1  = H2 - gl;
        float Q1  = (x1 > 0.f) ? __powf(x1, k1) : 0.f;
        float q2v = fminf(H2, gl) * k2;
        float Q2  = q2v * c23;
        float H3  = fmaf(q2v, k23, S3);
        float Q3  = fmaf(H3, k3, qb);
        S0 = H0 - qSm;
        Sv = Hv - qv;
        S2 = H2 - Q1 - q2v;
        S3 = H3 - Q3;

        __stcs(qout, Q1 + Q2 + Q3);
        qout += NS_ * NH_;
    }
}

// ============================================================================
// Kernel 4: causal 15-tap routing conv + ga-weighted h-reduction (parallel).
// block = (basin s, 256 timesteps)
// ============================================================================
__global__ void __launch_bounds__(256) k_route(float* __restrict__ out)
{
    __shared__ float sQ[270 * 20];      // rows t0-14..t0+255, stride 20 (16B-aligned)
    __shared__ float srr[15 * 16];      // d-major taps

    const int tid = threadIdx.x;
    const int s   = blockIdx.x;
    const int t0  = blockIdx.y << 8;

    for (int i = tid; i < 270 * 16; i += 256) {
        int row = i >> 4, h = i & 15;
        int tg = t0 + row - 14;
        sQ[row * 20 + h] = (tg >= 0 && tg < NT_)
                         ? g_Qs[(size_t)tg * (NS_ * NH_) + s * NH_ + h] : 0.f;
    }
    if (tid < 240) {
        int d = tid >> 4, h = tid & 15;
        srr[d * 16 + h] = g_rr[(s * NH_ + h) * 16 + d];
    }
    __syncthreads();

    const int t = t0 + tid;
    if (t < NT_) {
        float4 acc = make_float4(0.f, 0.f, 0.f, 0.f);
#pragma unroll
        for (int d = 0; d < 15; d++) {
            const float4* qr  = (const float4*)(sQ + (tid + 14 - d) * 20);
            const float4* rr4 = (const float4*)(srr + d * 16);
#pragma unroll
            for (int hq = 0; hq < 4; hq++) {
                float4 q = qr[hq];
                float4 r = rr4[hq];
                acc.x = fmaf(q.x, r.x, acc.x);
                acc.y = fmaf(q.y, r.y, acc.y);
                acc.z = fmaf(q.z, r.z, acc.z);
                acc.w = fmaf(q.w, r.w, acc.w);
            }
        }
        out[(size_t)t * NS_ + s] = (acc.x + acc.y) + (acc.z + acc.w);
    }
}

// ============================================================================
// launch
// ============================================================================
extern "C" void kernel_launch(void* const* d_in, const int* in_sizes, int n_in,
                              void* d_out, int out_size)
{
    const float* x       = (const float*)d_in[0];
    const float* xc      = (const float*)d_in[1];
    const float* fc_W1   = (const float*)d_in[2];
    const float* fc_b1   = (const float*)d_in[3];
    const float* fc_W2   = (const float*)d_in[4];
    const float* fc_b2   = (const float*)d_in[5];
    const float* fcR_W1  = (const float*)d_in[6];
    const float* fcR_b1  = (const float*)d_in[7];
    const float* fcR_W2  = (const float*)d_in[8];
    const float* fcR_b2  = (const float*)d_in[9];
    const float* fcT1_W1 = (const float*)d_in[10];
    const float* fcT1_b1 = (const float*)d_in[11];
    const float* fcT1_W2 = (const float*)d_in[12];
    const float* fcT1_b2 = (const float*)d_in[13];
    const float* fcT2_W1 = (const float*)d_in[14];
    const float* fcT2_b1 = (const float*)d_in[15];
    const float* fcT2_W2 = (const float*)d_in[16];
    const float* fcT2_b2 = (const float*)d_in[17];
    float* out = (float*)d_out;

    cudaFuncSetAttribute(k_mlp_tc, cudaFuncAttributeMaxDynamicSharedMemorySize, KM_SMEM_BYTES);

    k_hidden<<<NS_ / 8, 256>>>(xc, fc_W1, fc_b1, fcR_W1, fcR_b1,
                               fcT1_W1, fcT1_b1, fcT2_W1, fcT2_b1);
    k_outputs<<<NS_ / 8, 256>>>(fc_W2, fc_b2, fcR_W2, fcR_b2);
    k_prep<<<24, 256>>>(fcT1_W1, fcT1_W2, fcT1_b2, fcT2_W1, fcT2_W2, fcT2_b2);
    k_mlp_tc<<<dim3(NS_, 6), 128, KM_SMEM_BYTES>>>(x);
    k_scan2<<<(NS_ * NH_) / 32, 32>>>();
    k_route<<<dim3(NS_, 3), 256>>>(out);
}

// round 11
// speedup vs baseline: 2.8455x; 1.5019x over previous
#include <cuda_runtime.h>
#include <cuda_bf16.h>
#include <math.h>

// Problem dims
#define NT_ 730
#define NS_ 2000
#define NH_ 16
#define NG_ 32
#define NR_ 15

// ---------------- scratch (device globals; no allocations allowed) ----------------
__device__ float g_hfc [NS_ * 256];
__device__ float g_hR  [NS_ * 256];
__device__ float g_base1[NS_ * 256];
__device__ float g_base2[NS_ * 256];
__device__ float g_params[8][NS_ * NH_];
__device__ float g_rr  [NS_ * NH_ * 16];          // ga*relu(wR) taps, lag-indexed
__device__ uint2  g_PW  [6144];                   // W frag-packed, tf32 bits
__device__ float  g_c1  [256];                    // fcT1_W1 LAI col
__device__ float4 g_dvec[256];                    // fcT2_W1 {R,T1,T2} cols
__device__ float  g_bias48[48];
// fused per-lane scan inputs: {Pl1, Pl2, vk, vm}; +4 t-planes pad for prefetch
__device__ float4 g_v4 [(NT_ + 4) * NS_ * NH_];
__device__ float2 g_pe [(NT_ + 4) * NS_];         // per-(t,s): {Ps, E}
__device__ float  g_Qs [NT_ * NS_ * NH_];         // per-lane Q1+Q2+Q3

// ---------------- helpers ----------------
__device__ __forceinline__ float tanh_hw(float x) {
    float y;
    asm("tanh.approx.f32 %0, %1;" : "=f"(y) : "f"(x));
    return y;
}
__device__ __forceinline__ unsigned cvt_tf32(float f) {
    unsigned u;
    asm("cvt.rna.tf32.f32 %0, %1;" : "=r"(u) : "f"(f));
    return u;
}
#define MMA_TF32(D, a0, a1, a2, a3, b0, b1)                                   \
    asm("mma.sync.aligned.m16n8k8.row.col.f32.tf32.tf32.f32 "                 \
        "{%0,%1,%2,%3}, {%4,%5,%6,%7}, {%8,%9}, {%0,%1,%2,%3};"               \
        : "+f"((D)[0]), "+f"((D)[1]), "+f"((D)[2]), "+f"((D)[3])              \
        : "r"(a0), "r"(a1), "r"(a2), "r"(a3), "r"(b0), "r"(b1))

// ============================================================================
// Kernel 1a: per-basin hidden activations + time-invariant layer-1 bases
// ============================================================================
__global__ void __launch_bounds__(256) k_hidden(
    const float* __restrict__ xc,
    const float* __restrict__ fc_W1,  const float* __restrict__ fc_b1,
    const float* __restrict__ fcR_W1, const float* __restrict__ fcR_b1,
    const float* __restrict__ fcT1_W1, const float* __restrict__ fcT1_b1,
    const float* __restrict__ fcT2_W1, const float* __restrict__ fcT2_b1)
{
    __shared__ float xcs[8][NG_];
    const int tid = threadIdx.x;
    const int s0  = blockIdx.x * 8;
    xcs[tid >> 5][tid & 31] = xc[s0 * NG_ + tid];
    __syncthreads();

    const int j = tid;
    float acc[8];

    {
        float b = fc_b1[j];
#pragma unroll
        for (int i = 0; i < 8; i++) acc[i] = b;
        const float4* row = (const float4*)(fc_W1 + j * NG_);
#pragma unroll
        for (int q = 0; q < 8; q++) {
            float4 w = row[q];
#pragma unroll
            for (int i = 0; i < 8; i++) {
                acc[i] = fmaf(w.x, xcs[i][4*q+0], acc[i]);
                acc[i] = fmaf(w.y, xcs[i][4*q+1], acc[i]);
                acc[i] = fmaf(w.z, xcs[i][4*q+2], acc[i]);
                acc[i] = fmaf(w.w, xcs[i][4*q+3], acc[i]);
            }
        }
#pragma unroll
        for (int i = 0; i < 8; i++) g_hfc[(s0 + i) * 256 + j] = tanhf(acc[i]);
    }
    {
        float b = fcR_b1[j];
#pragma unroll
        for (int i = 0; i < 8; i++) acc[i] = b;
        const float4* row = (const float4*)(fcR_W1 + j * NG_);
#pragma unroll
        for (int q = 0; q < 8; q++) {
            float4 w = row[q];
#pragma unroll
            for (int i = 0; i < 8; i++) {
                acc[i] = fmaf(w.x, xcs[i][4*q+0], acc[i]);
                acc[i] = fmaf(w.y, xcs[i][4*q+1], acc[i]);
                acc[i] = fmaf(w.z, xcs[i][4*q+2], acc[i]);
                acc[i] = fmaf(w.w, xcs[i][4*q+3], acc[i]);
            }
        }
#pragma unroll
        for (int i = 0; i < 8; i++) g_hR[(s0 + i) * 256 + j] = tanhf(acc[i]);
    }
    {
        float b = fcT1_b1[j];
#pragma unroll
        for (int i = 0; i < 8; i++) acc[i] = b;
        const float* row = fcT1_W1 + j * 33 + 1;
#pragma unroll
        for (int g = 0; g < NG_; g++) {
            float w = row[g];
#pragma unroll
            for (int i = 0; i < 8; i++) acc[i] = fmaf(w, xcs[i][g], acc[i]);
        }
#pragma unroll
        for (int i = 0; i < 8; i++) g_base1[(s0 + i) * 256 + j] = acc[i];
    }
    {
        float b = fcT2_b1[j];
#pragma unroll
        for (int i = 0; i < 8; i++) acc[i] = b;
        const float* row = fcT2_W1 + j * 35 + 3;
#pragma unroll
        for (int g = 0; g < NG_; g++) {
            float w = row[g];
#pragma unroll
            for (int i = 0; i < 8; i++) acc[i] = fmaf(w, xcs[i][g], acc[i]);
        }
#pragma unroll
        for (int i = 0; i < 8; i++) g_base2[(s0 + i) * 256 + j] = acc[i];
    }
}

// ============================================================================
// Kernel 1b: per-basin output layers -> scan params + routing taps
// ============================================================================
__global__ void __launch_bounds__(256) k_outputs(
    const float* __restrict__ fc_W2,  const float* __restrict__ fc_b2,
    const float* __restrict__ fcR_W2, const float* __restrict__ fcR_b2)
{
    __shared__ float hf[8][256];
    __shared__ float hr[8][256];
    __shared__ float w8[8][160];
    __shared__ float r8[8][240];
    __shared__ float ga8[8][NH_];

    const int tid = threadIdx.x;
    const int s0  = blockIdx.x * 8;

    for (int idx = tid; idx < 2048; idx += 256) {
        int b = idx >> 8, j = idx & 255;
        hf[b][j] = g_hfc[(s0 + b) * 256 + j];
        hr[b][j] = g_hR [(s0 + b) * 256 + j];
    }
    __syncthreads();

    if (tid < 160) {
        const int o = tid;
        float acc[8];
        float bb = fc_b2[o];
#pragma unroll
        for (int i = 0; i < 8; i++) acc[i] = bb;
        const float4* row = (const float4*)(fc_W2 + o * 256);
        for (int q = 0; q < 64; q++) {
            float4 w = row[q];
#pragma unroll
            for (int i = 0; i < 8; i++) {
                acc[i] = fmaf(w.x, hf[i][4*q+0], acc[i]);
                acc[i] = fmaf(w.y, hf[i][4*q+1], acc[i]);
                acc[i] = fmaf(w.z, hf[i][4*q+2], acc[i]);
                acc[i] = fmaf(w.w, hf[i][4*q+3], acc[i]);
            }
        }
#pragma unroll
        for (int i = 0; i < 8; i++) w8[i][o] = acc[i];
    }
    if (tid < 240) {
        const int o = tid;
        float acc[8];
        float bb = fcR_b2[o];
#pragma unroll
        for (int i = 0; i < 8; i++) acc[i] = bb;
        const float4* row = (const float4*)(fcR_W2 + o * 256);
        for (int q = 0; q < 64; q++) {
            float4 w = row[q];
#pragma unroll
            for (int i = 0; i < 8; i++) {
                acc[i] = fmaf(w.x, hr[i][4*q+0], acc[i]);
                acc[i] = fmaf(w.y, hr[i][4*q+1], acc[i]);
                acc[i] = fmaf(w.z, hr[i][4*q+2], acc[i]);
                acc[i] = fmaf(w.w, hr[i][4*q+3], acc[i]);
            }
        }
#pragma unroll
        for (int i = 0; i < 8; i++) r8[i][o] = fmaxf(acc[i], 0.f);
    }
    __syncthreads();

    if (tid < 128) {
        const int b = tid >> 4, h = tid & 15;
        const float* wb = w8[b];
        float k1  = 1.f / (1.f + expf(-wb[16  + h]));
        float k2  = 1.f / (1.f + expf(-wb[32  + h]));
        float k23 = 1.f / (1.f + expf(-wb[48  + h]));
        float k3  = (1.f / (1.f + expf(-wb[64 + h]))) * 0.1f;
        float gl  = expf(wb[80 + h]) * 2.f;
        float qb  = fmaxf(wb[112 + h], 0.f);
        float ge1 = fmaxf(wb[128 + h], 0.f);
        float ge2 = fmaxf(wb[144 + h], 0.f);
        float m = wb[96];
        for (int i = 1; i < 16; i++) m = fmaxf(m, wb[96 + i]);
        float sum = 0.f;
        for (int i = 0; i < 16; i++) sum += expf(wb[96 + i] - m);
        float ga = expf(wb[96 + h] - m) / sum;
        ga8[b][h] = ga;

        const int lane = (s0 + b) * NH_ + h;
        g_params[0][lane] = k1;
        g_params[1][lane] = k2;
        g_params[2][lane] = k23;
        g_params[3][lane] = k3;
        g_params[4][lane] = gl;
        g_params[5][lane] = qb;
        g_params[6][lane] = ge1;
        g_params[7][lane] = ge2;
        g_rr[lane * 16 + 15] = 0.f;
    }
    __syncthreads();

    for (int idx = tid; idx < 8 * 240; idx += 256) {
        int b = idx / 240, o = idx % 240;
        int h = o / NR_, jj = o % NR_;
        int lane = (s0 + b) * NH_ + h;
        g_rr[lane * 16 + (14 - jj)] = ga8[b][h] * r8[b][o];
    }
}

// ============================================================================
// Kernel 1c: pack layer-2 weights into mma B-fragment layout (tf32 bits)
// ============================================================================
__global__ void __launch_bounds__(256) k_prep(
    const float* __restrict__ fcT1_W1, const float* __restrict__ fcT1_W2,
    const float* __restrict__ fcT1_b2,
    const float* __restrict__ fcT2_W1, const float* __restrict__ fcT2_W2,
    const float* __restrict__ fcT2_b2)
{
    const int idx = blockIdx.x * 256 + threadIdx.x;   // 0..6143
    {
        const int kk   = idx / 192;
        const int rem  = idx % 192;
        const int nt   = rem / 32;
        const int lane = rem % 32;
        const int j    = kk * 8 + (lane & 3);
        const int oo   = lane >> 2;
        float w0, w1;
        if (nt < 4) {
            int o = nt * 8 + oo;
            w0 = fcT1_W2[o * 256 + j];
            w1 = fcT1_W2[o * 256 + j + 4];
        } else {
            int o = (nt - 4) * 8 + oo;
            w0 = fcT2_W2[o * 256 + j];
            w1 = fcT2_W2[o * 256 + j + 4];
        }
        uint2 u;
        u.x = cvt_tf32(w0);
        u.y = cvt_tf32(w1);
        g_PW[idx] = u;
    }
    if (idx < 256) {
        g_c1[idx] = fcT1_W1[idx * 33];
        float4 dv;
        dv.x = fcT2_W1[idx * 35 + 0];
        dv.y = fcT2_W1[idx * 35 + 1];
        dv.z = fcT2_W1[idx * 35 + 2];
        dv.w = 0.f;
        g_dvec[idx] = dv;
    }
    if (idx < 48) g_bias48[idx] = (idx < 32) ? fcT1_b2[idx] : fcT2_b2[idx - 32];
}

// ============================================================================
// Kernel 2: tensor-core per-(t,s) MLPs -> {Pl1,Pl2,vk,vm} + {Ps,E}
// block = 2 basins x 128 timesteps, 8 warps (4 per basin); register epilogue
// ============================================================================
// smem word offsets
#define SMO_DVEC  0                       // float4[256]        -> 1024 words
#define SMO_PW    1024                    // uint2[6144]        -> 12288
#define SMO_COEF1 13312                   // float2[2*256]      -> 1024
#define SMO_BASE2 14336                   // float [2*256]      -> 512
#define SMO_XS    14848                   // float4[2*128]      -> 1024 {Ta,Tb,Rv,LAI}
#define SMO_PL    15872                   // float [2*128]      -> 256
#define SMO_BIAS  16128                   // float [48]
#define KM_SMEM_WORDS 16176
#define KM_SMEM_BYTES (KM_SMEM_WORDS * 4)

__global__ void __launch_bounds__(256) k_mlp_tc(const float* __restrict__ x)
{
    extern __shared__ float sm[];
    float4* sdvec  = (float4*)(sm + SMO_DVEC);
    uint2*  sPW    = (uint2*)(sm + SMO_PW);
    float2* scoef1 = (float2*)(sm + SMO_COEF1);
    float*  sbase2 = sm + SMO_BASE2;
    float4* sxs    = (float4*)(sm + SMO_XS);
    float*  sPL    = sm + SMO_PL;
    float*  sbias  = sm + SMO_BIAS;

    const int tid = threadIdx.x;
    const int s0  = blockIdx.x * 2;
    const int t0  = blockIdx.y << 7;

    for (int i = tid; i < 6144; i += 256) sPW[i] = g_PW[i];
    for (int i = tid; i < 256; i += 256) sdvec[i] = g_dvec[i];
    for (int i = tid; i < 512; i += 256) {
        int g = i >> 8, j = i & 255;
        scoef1[i] = make_float2(g_base1[(s0 + g) * 256 + j], g_c1[j]);
        sbase2[i] = g_base2[(s0 + g) * 256 + j];
    }
    if (tid < 48) sbias[tid] = g_bias48[tid];

    // prologue: one thread per (basin, row): forcings + vp/Ps/Pl
    {
        const int g = tid >> 7, r = tid & 127;
        const int t = t0 + r;
        const int s = s0 + g;
        float P = 0.f, E = 0.f, Ta = 0.f, Tb = 0.f, Rv = 0.f, LAI = 0.f;
        if (t < NT_) {
            const float* xr = x + ((size_t)t * NS_ + s) * 6;
            P = __ldg(xr); E = __ldg(xr + 1); Ta = __ldg(xr + 2);
            Tb = __ldg(xr + 3); Rv = __ldg(xr + 4); LAI = __ldg(xr + 5);
        }
        sxs[g * 128 + r] = make_float4(Ta, Tb, Rv, LAI);

        float den = Tb - Ta;
        float ra  = (Ta + Tb) / (den == 0.f ? 1.f : den);
        ra = fminf(fmaxf(ra, -1.f), 1.f);
        if (Ta >= 0.f || Tb <= 0.f) ra = 0.f;
        float vp = 1.f - acosf(ra) * (1.f / 3.1415f);
        if (Ta >= 0.f) vp = 1.f;
        if (Tb <= 0.f) vp = 0.f;
        float Ps = P * (1.f - vp);
        float Pl = P * vp;
        sPL[g * 128 + r] = Pl;
        if (t < NT_) __stcs(g_pe + (size_t)t * NS_ + s, make_float2(Ps, E));
    }
    __syncthreads();

    const int g    = tid >> 7;
    const int wl   = (tid >> 5) & 3;
    const int lane = tid & 31;
    const int rq = lane >> 2, qk = lane & 3;
    const int rbase = wl * 32 + rq;
    const int s = s0 + g;

    float LAI[4], Rv[4], Ta[4], Tb[4];
#pragma unroll
    for (int i = 0; i < 4; i++) {
        float4 xr = sxs[g * 128 + rbase + i * 8];
        Ta[i] = xr.x; Tb[i] = xr.y; Rv[i] = xr.z; LAI[i] = xr.w;
    }

    float dacc[2][6][4];
#pragma unroll
    for (int mt = 0; mt < 2; mt++)
#pragma unroll
        for (int nt = 0; nt < 6; nt++)
#pragma unroll
            for (int r = 0; r < 4; r++) dacc[mt][nt][r] = 0.f;

#pragma unroll 2
    for (int kk = 0; kk < 32; kk++) {
        const int j0 = kk * 8 + qk;
        const uint2* pb = sPW + kk * 192 + lane;

        // ---- G1: h1 = tanh(base1 + LAI*c1), n-tiles 0..3 (vi, vk) ----
        float2 c0  = scoef1[g * 256 + j0];
        float2 c1v = scoef1[g * 256 + j0 + 4];
        unsigned aA[8];
#pragma unroll
        for (int i = 0; i < 4; i++) {
            float hA = tanh_hw(fmaf(LAI[i], c0.y,  c0.x));
            float hB = tanh_hw(fmaf(LAI[i], c1v.y, c1v.x));
            aA[(i >> 1) * 4 + (i & 1)]     = __float_as_uint(hA);   // HW truncates to tf32
            aA[(i >> 1) * 4 + 2 + (i & 1)] = __float_as_uint(hB);
        }
#pragma unroll
        for (int nt = 0; nt < 4; nt++) {
            uint2 b = pb[nt * 32];
            MMA_TF32(dacc[0][nt], aA[0], aA[1], aA[2], aA[3], b.x, b.y);
            MMA_TF32(dacc[1][nt], aA[4], aA[5], aA[6], aA[7], b.x, b.y);
        }

        // ---- G2: h2 = tanh(base2 + R*d0 + T1*d1 + T2*d2), n-tiles 4..5 (vm) ----
        float  b20 = sbase2[g * 256 + j0], b21 = sbase2[g * 256 + j0 + 4];
        float4 dv0 = sdvec[j0],  dv1 = sdvec[j0 + 4];
        unsigned aB[8];
#pragma unroll
        for (int i = 0; i < 4; i++) {
            float p = fmaf(Rv[i], dv0.x, b20);
            p = fmaf(Ta[i], dv0.y, p);
            p = fmaf(Tb[i], dv0.z, p);
            float q = fmaf(Rv[i], dv1.x, b21);
            q = fmaf(Ta[i], dv1.y, q);
            q = fmaf(Tb[i], dv1.z, q);
            aB[(i >> 1) * 4 + (i & 1)]     = __float_as_uint(tanh_hw(p));
            aB[(i >> 1) * 4 + 2 + (i & 1)] = __float_as_uint(tanh_hw(q));
        }
#pragma unroll
        for (int nt = 4; nt < 6; nt++) {
            uint2 b = pb[nt * 32];
            MMA_TF32(dacc[0][nt], aB[0], aB[1], aB[2], aB[3], b.x, b.y);
            MMA_TF32(dacc[1][nt], aB[4], aB[5], aB[6], aB[7], b.x, b.y);
        }
    }

    // register epilogue: thread owns rows {wl*32+mt*16+rq, +8}, h = {hi*8+2qk, +1}
    const float inv6 = 1.f / 6.f;
#pragma unroll
    for (int mt = 0; mt < 2; mt++) {
#pragma unroll
        for (int half = 0; half < 2; half++) {
            const int r = wl * 32 + mt * 16 + rq + half * 8;
            const int t = t0 + r;
            if (t < NT_) {
                const float Pl = sPL[g * 128 + r];
                float4* dst = g_v4 + ((size_t)t * NS_ + s) * NH_;
#pragma unroll
                for (int hi = 0; hi < 2; hi++) {
#pragma unroll
                    for (int c = 0; c < 2; c++) {
                        const int h  = hi * 8 + 2 * qk + c;
                        const int di = half * 2 + c;
                        float vi = __saturatef(fmaf(dacc[mt][hi][di]     + sbias[h],      inv6, 0.5f));
                        float vk = __saturatef(fmaf(dacc[mt][2 + hi][di] + sbias[16 + h], inv6, 0.5f));
                        float vm = __expf(2.f * (dacc[mt][4 + hi][di] + sbias[32 + h]));
                        float Pl2 = Pl * vi;
                        __stcs(dst + h, make_float4(Pl - Pl2, Pl2, vk, vm));
                    }
                }
            }
        }
    }
}

// ============================================================================
// Kernel 3: pure recurrence; 2 independent (s,h) lanes per thread for ILP.
// ============================================================================
__global__ void __launch_bounds__(32) k_scan2()
{
    const int l0 = blockIdx.x * 32 + threadIdx.x;   // 0..15999
    const int l1 = l0 + 16000;

    const float k1a  = g_params[0][l0], k1b  = g_params[0][l1];
    const float k2a  = g_params[1][l0], k2b  = g_params[1][l1];
    const float k23a = g_params[2][l0], k23b = g_params[2][l1];
    const float k3a  = g_params[3][l0], k3b  = g_params[3][l1];
    const float gla  = g_params[4][l0], glb  = g_params[4][l1];
    const float qba  = g_params[5][l0], qbb  = g_params[5][l1];
    const float ge1a = g_params[6][l0], ge1b = g_params[6][l1];
    const float ge2a = g_params[7][l0], ge2b = g_params[7][l1];
    const float c23a = 1.f - k23a,      c23b = 1.f - k23b;

    const float4* pva = g_v4 + l0;
    const float4* pvb = g_v4 + l1;
    const float2* ppa = g_pe + (l0 >> 4);
    const float2* ppb = g_pe + (l1 >> 4);

    float4 va0 = __ldcs(pva),               vb0 = __ldcs(pvb);
    float4 va1 = __ldcs(pva + NS_ * NH_),   vb1 = __ldcs(pvb + NS_ * NH_);
    float4 va2 = __ldcs(pva + 2*NS_*NH_),   vb2 = __ldcs(pvb + 2*NS_*NH_);
    float2 qa0 = __ldcs(ppa),               qb0 = __ldcs(ppb);
    float2 qa1 = __ldcs(ppa + NS_),         qb1 = __ldcs(ppb + NS_);
    float2 qa2 = __ldcs(ppa + 2*NS_),       qb2 = __ldcs(ppb + 2*NS_);

    float S0a = 0.f, Sva = 0.f, S2a = 0.f, S3a = 0.f;
    float S0b = 0.f, Svb = 0.f, S2b = 0.f, S3b = 0.f;
    float* qouta = g_Qs + l0;
    float* qoutb = g_Qs + l1;

#pragma unroll 2
    for (int t = 0; t < NT_; t++) {
        float4 va = va0; va0 = va1; va1 = va2;
        va2 = __ldcs(pva + 3 * NS_ * NH_); pva += NS_ * NH_;
        float4 vb = vb0; vb0 = vb1; vb1 = vb2;
        vb2 = __ldcs(pvb + 3 * NS_ * NH_); pvb += NS_ * NH_;
        float2 pea = qa0; qa0 = qa1; qa1 = qa2;
        qa2 = __ldcs(ppa + 3 * NS_); ppa += NS_;
        float2 peb = qb0; qb0 = qb1; qb1 = qb2;
        qb2 = __ldcs(ppb + 3 * NS_); ppb += NS_;

        // lane A
        {
            float H0  = S0a + pea.x;
            float qSm = fminf(H0, va.w);
            float Hv  = fmaxf(Sva + va.x - pea.y * ge1a, 0.f);
            float qv  = Sva * va.z;
            float H2  = fmaxf(S2a + qSm + qv - pea.y * ge2a + va.y, 0.f);
            float x1  = H2 - gla;
            float Q1  = (x1 > 0.f) ? __powf(x1, k1a) : 0.f;
            float q2v = fminf(H2, gla) * k2a;
            float H3  = fmaf(q2v, k23a, S3a);
            float Q3  = fmaf(H3, k3a, qba);
            S0a = H0 - qSm;
            Sva = Hv - qv;
            S2a = H2 - Q1 - q2v;
            S3a = H3 - Q3;
            __stcs(qouta, Q1 + q2v * c23a + Q3);
            qouta += NS_ * NH_;
        }
        // lane B
        {
            float H0  = S0b + peb.x;
            float qSm = fminf(H0, vb.w);
            float Hv  = fmaxf(Svb + vb.x - peb.y * ge1b, 0.f);
            float qv  = Svb * vb.z;
            float H2  = fmaxf(S2b + qSm + qv - peb.y * ge2b + vb.y, 0.f);
            float x1  = H2 - glb;
            float Q1  = (x1 > 0.f) ? __powf(x1, k1b) : 0.f;
            float q2v = fminf(H2, glb) * k2b;
            float H3  = fmaf(q2v, k23b, S3b);
            float Q3  = fmaf(H3, k3b, qbb);
            S0b = H0 - qSm;
            Svb = Hv - qv;
            S2b = H2 - Q1 - q2v;
            S3b = H3 - Q3;
            __stcs(qoutb, Q1 + q2v * c23b + Q3);
            qoutb += NS_ * NH_;
        }
    }
}

// ============================================================================
// Kernel 4: causal 15-tap routing conv + h-reduction (parallel).
// ============================================================================
__global__ void __launch_bounds__(256) k_route(float* __restrict__ out)
{
    __shared__ float sQ[270 * 20];
    __shared__ float srr[15 * 16];

    const int tid = threadIdx.x;
    const int s   = blockIdx.x;
    const int t0  = blockIdx.y << 8;

    for (int i = tid; i < 270 * 16; i += 256) {
        int row = i >> 4, h = i & 15;
        int tg = t0 + row - 14;
        sQ[row * 20 + h] = (tg >= 0 && tg < NT_)
                         ? g_Qs[(size_t)tg * (NS_ * NH_) + s * NH_ + h] : 0.f;
    }
    if (tid < 240) {
        int d = tid >> 4, h = tid & 15;
        srr[d * 16 + h] = g_rr[(s * NH_ + h) * 16 + d];
    }
    __syncthreads();

    const int t = t0 + tid;
    if (t < NT_) {
        float4 acc = make_float4(0.f, 0.f, 0.f, 0.f);
#pragma unroll
        for (int d = 0; d < 15; d++) {
            const float4* qr  = (const float4*)(sQ + (tid + 14 - d) * 20);
            const float4* rr4 = (const float4*)(srr + d * 16);
#pragma unroll
            for (int hq = 0; hq < 4; hq++) {
                float4 q = qr[hq];
                float4 r = rr4[hq];
                acc.x = fmaf(q.x, r.x, acc.x);
                acc.y = fmaf(q.y, r.y, acc.y);
                acc.z = fmaf(q.z, r.z, acc.z);
                acc.w = fmaf(q.w, r.w, acc.w);
            }
        }
        out[(size_t)t * NS_ + s] = (acc.x + acc.y) + (acc.z + acc.w);
    }
}

// ============================================================================
// launch
// ============================================================================
extern "C" void kernel_launch(void* const* d_in, const int* in_sizes, int n_in,
                              void* d_out, int out_size)
{
    const float* x       = (const float*)d_in[0];
    const float* xc      = (const float*)d_in[1];
    const float* fc_W1   = (const float*)d_in[2];
    const float* fc_b1   = (const float*)d_in[3];
    const float* fc_W2   = (const float*)d_in[4];
    const float* fc_b2   = (const float*)d_in[5];
    const float* fcR_W1  = (const float*)d_in[6];
    const float* fcR_b1  = (const float*)d_in[7];
    const float* fcR_W2  = (const float*)d_in[8];
    const float* fcR_b2  = (const float*)d_in[9];
    const float* fcT1_W1 = (const float*)d_in[10];
    const float* fcT1_b1 = (const float*)d_in[11];
    const float* fcT1_W2 = (const float*)d_in[12];
    const float* fcT1_b2 = (const float*)d_in[13];
    const float* fcT2_W1 = (const float*)d_in[14];
    const float* fcT2_b1 = (const float*)d_in[15];
    const float* fcT2_W2 = (const float*)d_in[16];
    const float* fcT2_b2 = (const float*)d_in[17];
    float* out = (float*)d_out;

    cudaFuncSetAttribute(k_mlp_tc, cudaFuncAttributeMaxDynamicSharedMemorySize, KM_SMEM_BYTES);

    k_hidden<<<NS_ / 8, 256>>>(xc, fc_W1, fc_b1, fcR_W1, fcR_b1,
                               fcT1_W1, fcT1_b1, fcT2_W1, fcT2_b1);
    k_outputs<<<NS_ / 8, 256>>>(fc_W2, fc_b2, fcR_W2, fcR_b2);
    k_prep<<<24, 256>>>(fcT1_W1, fcT1_W2, fcT1_b2, fcT2_W1, fcT2_W2, fcT2_b2);
    k_mlp_tc<<<dim3(NS_ / 2, 6), 256, KM_SMEM_BYTES>>>(x);
    k_scan2<<<500, 32>>>();
    k_route<<<dim3(NS_, 3), 256>>>(out);
}